// round 10
// baseline (speedup 1.0000x reference)
#include <cuda_runtime.h>

// Scratch: [0]=sum|r-t|, [1]=sum g, [2]=sum|g-mu|
// Zero at module load; reset by the exit-ticket CTA each run (replay-safe).
__device__ double g_acc[3];
// Monotone counters (never reset -> no reset/spin race across graph replays)
__device__ unsigned int g_bar[2];   // [0] mid grid barrier, [1] exit ticket

struct F8 { float v[8]; };

static __device__ __forceinline__ float warp_reduce(float v) {
    #pragma unroll
    for (int o = 16; o > 0; o >>= 1) v += __shfl_down_sync(0xFFFFFFFFu, v, o);
    return v;
}

// 32B load, lowest L2 priority: the r/t stream evicts itself, not g
static __device__ __forceinline__ F8 ld_ef(const float* p) {
    F8 r;
    asm("ld.global.nc.L2::evict_first.v8.b32 {%0,%1,%2,%3,%4,%5,%6,%7}, [%8];"
        : "=f"(r.v[0]), "=f"(r.v[1]), "=f"(r.v[2]), "=f"(r.v[3]),
          "=f"(r.v[4]), "=f"(r.v[5]), "=f"(r.v[6]), "=f"(r.v[7]) : "l"(p));
    return r;
}
// 32B load, highest L2 priority: pin g for the phase-2 re-read
static __device__ __forceinline__ F8 ld_el(const float* p) {
    F8 r;
    asm("ld.global.nc.L2::evict_last.v8.b32 {%0,%1,%2,%3,%4,%5,%6,%7}, [%8];"
        : "=f"(r.v[0]), "=f"(r.v[1]), "=f"(r.v[2]), "=f"(r.v[3]),
          "=f"(r.v[4]), "=f"(r.v[5]), "=f"(r.v[6]), "=f"(r.v[7]) : "l"(p));
    return r;
}
// plain 32B load (phase-2 g: expected L2 hit)
static __device__ __forceinline__ F8 ld_nc(const float* p) {
    F8 r;
    asm("ld.global.nc.v8.b32 {%0,%1,%2,%3,%4,%5,%6,%7}, [%8];"
        : "=f"(r.v[0]), "=f"(r.v[1]), "=f"(r.v[2]), "=f"(r.v[3]),
          "=f"(r.v[4]), "=f"(r.v[5]), "=f"(r.v[6]), "=f"(r.v[7]) : "l"(p));
    return r;
}

__global__ void __launch_bounds__(512, 3)
k_fused(const float* __restrict__ r, const float* __restrict__ t,
        const float* __restrict__ g, float* __restrict__ out,
        int n8, unsigned int nCTA) {
    const int tid    = blockIdx.x * blockDim.x + threadIdx.x;
    const int stride = gridDim.x * blockDim.x;
    const int lane   = threadIdx.x & 31;
    const int wid    = threadIdx.x >> 5;
    const int nwarp  = blockDim.x >> 5;

    __shared__ float sh0[16], sh1[16];
    __shared__ float s_mu;

    // ---- Phase 1: sum g (64 MB DRAM; evict_last pins g in L2) ----
    float s1 = 0.0f;
    #pragma unroll 2
    for (int i = tid; i < n8; i += stride) {
        F8 c = ld_el(g + (long)i * 8);
        float p0 = (c.v[0] + c.v[1]) + (c.v[2] + c.v[3]);
        float p1 = (c.v[4] + c.v[5]) + (c.v[6] + c.v[7]);
        s1 += p0 + p1;
    }
    s1 = warp_reduce(s1);
    if (lane == 0) sh1[wid] = s1;
    __syncthreads();
    if (wid == 0) {
        float x1 = (lane < nwarp) ? sh1[lane] : 0.0f;
        x1 = warp_reduce(x1);
        if (lane == 0) atomicAdd(&g_acc[1], (double)x1);
    }

    // ---- Epoch grid barrier (monotone counter; replay-safe) ----
    if (threadIdx.x == 0) {
        __threadfence();
        unsigned int tkt    = atomicAdd(&g_bar[0], 1u);
        unsigned int target = (tkt / nCTA + 1u) * nCTA;
        while (*(volatile unsigned int*)&g_bar[0] < target) { __nanosleep(32); }
        double sum = *(volatile double*)&g_acc[1];
        s_mu = (float)(sum / ((double)n8 * 8.0));
    }
    __syncthreads();
    const float mu = s_mu;

    // ---- Phase 2: r/t DRAM stream (evict_first) + g L2 re-read, fused ----
    float s0 = 0.0f, s2 = 0.0f;
    for (int i = tid; i < n8; i += stride) {
        const long off = (long)i * 8;
        F8 a = ld_ef(r + off);
        F8 b = ld_ef(t + off);
        F8 c = ld_nc(g + off);
        #pragma unroll
        for (int j = 0; j < 8; j++) {
            s0 += fabsf(a.v[j] - b.v[j]);
            s2 += fabsf(c.v[j] - mu);
        }
    }
    s0 = warp_reduce(s0);
    s2 = warp_reduce(s2);
    if (lane == 0) { sh0[wid] = s0; sh1[wid] = s2; }
    __syncthreads();
    if (wid == 0) {
        float x0 = (lane < nwarp) ? sh0[lane] : 0.0f;
        float x2 = (lane < nwarp) ? sh1[lane] : 0.0f;
        x0 = warp_reduce(x0);
        x2 = warp_reduce(x2);
        if (lane == 0) {
            atomicAdd(&g_acc[0], (double)x0);
            atomicAdd(&g_acc[2], (double)x2);
        }
    }

    // ---- Exit ticket: last CTA finalizes scalar + resets accumulators ----
    if (threadIdx.x == 0) {
        __threadfence();
        unsigned int tkt = atomicAdd(&g_bar[1], 1u);
        if ((tkt + 1u) % nCTA == 0u) {
            double a0  = *(volatile double*)&g_acc[0];
            double a2  = *(volatile double*)&g_acc[2];
            double n_d = (double)n8 * 8.0;
            out[0] = (float)((a0 + 100.0 * a2) / n_d);
            g_acc[0] = 0.0; g_acc[1] = 0.0; g_acc[2] = 0.0;  // ready for next replay
            __threadfence();
        }
    }
}

extern "C" void kernel_launch(void* const* d_in, const int* in_sizes, int n_in,
                              void* d_out, int out_size) {
    const float* resnet = (const float*)d_in[0];
    const float* gru    = (const float*)d_in[1];
    const float* target = (const float*)d_in[2];
    float* out = (float*)d_out;

    const int n  = in_sizes[0];
    const int n8 = n >> 3;               // 256-bit chunks

    const int block = 512;
    const unsigned int grid = 148u * 3u;   // 48 warps/SM

    k_fused<<<grid, block>>>(resnet, target, gru, out, n8, grid);
}